// round 10
// baseline (speedup 1.0000x reference)
#include <cuda_runtime.h>

#define DIM 1024
#define TPB 256          // thread t owns float4 column t of each 1024-float row
#define ROW_UNROLL 16    // 2048 blocks * 16 rows = 32768 rows, exact

__global__ __launch_bounds__(TPB) void fused_mask_mul_kernel(
    const float4* __restrict__ x4,
    const float4* __restrict__ mask_param4,
    const float4* __restrict__ mvec4,
    float4* __restrict__ out4,
    int nrows)                      // nrows = n / 1024
{
    const int t = threadIdx.x;
    __shared__ float red[8];        // 8 warps per block

    const size_t rowq = DIM / 4;
    size_t base = (size_t)blockIdx.x * ROW_UNROLL * rowq + t;
    const int row0 = blockIdx.x * ROW_UNROLL;
    const bool full_strip = (row0 + ROW_UNROLL <= nrows);

    // ---- issue the block's strip loads FIRST (independent of the mask) ----
    float4 v[ROW_UNROLL];
    if (full_strip) {
        #pragma unroll
        for (int r = 0; r < ROW_UNROLL; r++)
            v[r] = __ldcs(&x4[base + (size_t)r * rowq]);
    }

    // ---- softmax computed while the loads are in flight ----
    float4 p = mask_param4[t];

    float m = fmaxf(fmaxf(p.x, p.y), fmaxf(p.z, p.w));
    #pragma unroll
    for (int o = 16; o; o >>= 1) m = fmaxf(m, __shfl_xor_sync(0xFFFFFFFFu, m, o));
    if ((t & 31) == 0) red[t >> 5] = m;
    __syncthreads();
    float maxv = red[0];
    #pragma unroll
    for (int i = 1; i < 8; i++) maxv = fmaxf(maxv, red[i]);
    __syncthreads();

    float e0 = __expf(p.x - maxv);
    float e1 = __expf(p.y - maxv);
    float e2 = __expf(p.z - maxv);
    float e3 = __expf(p.w - maxv);

    float s = e0 + e1 + e2 + e3;
    #pragma unroll
    for (int o = 16; o; o >>= 1) s += __shfl_xor_sync(0xFFFFFFFFu, s, o);
    if ((t & 31) == 0) red[t >> 5] = s;
    __syncthreads();
    float sum = 0.f;
    #pragma unroll
    for (int i = 0; i < 8; i++) sum += red[i];

    float4 mv = mvec4[t];
    float inv = (float)DIM / sum;   // PRUNE_RATE = 1.0
    float4 mk;
    mk.x = e0 * inv * mv.x;
    mk.y = e1 * inv * mv.y;
    mk.z = e2 * inv * mv.z;
    mk.w = e3 * inv * mv.w;

    // mask tail: out[n .. n+1023], written once by block 0
    if (blockIdx.x == 0)
        out4[(size_t)nrows * rowq + t] = mk;

    // ---- multiply + store the strip ----
    if (full_strip) {
        #pragma unroll
        for (int r = 0; r < ROW_UNROLL; r++) {
            v[r].x *= mk.x; v[r].y *= mk.y; v[r].z *= mk.z; v[r].w *= mk.w;
            __stcs(&out4[base + (size_t)r * rowq], v[r]);
        }
    } else {
        // partial strip at the end (bench shape divides evenly; safety path)
        for (int row = row0; row < nrows; row++, base += rowq) {
            float4 w = __ldcs(&x4[base]);
            w.x *= mk.x; w.y *= mk.y; w.z *= mk.z; w.w *= mk.w;
            __stcs(&out4[base], w);
        }
    }
}

extern "C" void kernel_launch(void* const* d_in, const int* in_sizes, int n_in,
                              void* d_out, int out_size) {
    const float* x          = (const float*)d_in[0];  // [8,4096,1024] fp32
    const float* mask_param = (const float*)d_in[1];  // [1024]
    const float* mvec       = (const float*)d_in[2];  // [1024]

    int n = in_sizes[0];
    int nrows = n / DIM;
    int blocks = (nrows + ROW_UNROLL - 1) / ROW_UNROLL;  // 2048 for bench shape

    fused_mask_mul_kernel<<<blocks, TPB>>>(
        (const float4*)x, (const float4*)mask_param, (const float4*)mvec,
        (float4*)d_out, nrows);
}

// round 11
// speedup vs baseline: 1.0292x; 1.0292x over previous
#include <cuda_runtime.h>

#define DIM 1024
#define TPB 256          // thread t owns float4 column t of each 1024-float row
#define ROW_UNROLL 8     // measured-best: 4096 blocks * 8 rows = 32768 rows, exact

__global__ __launch_bounds__(TPB) void fused_mask_mul_kernel(
    const float4* __restrict__ x4,
    const float4* __restrict__ mask_param4,
    const float4* __restrict__ mvec4,
    float4* __restrict__ out4,
    int nrows)                      // nrows = n / 1024
{
    const int t = threadIdx.x;
    __shared__ float red[8];        // 8 warps per block

    const size_t rowq = DIM / 4;
    size_t base = (size_t)blockIdx.x * ROW_UNROLL * rowq + t;
    const int row0 = blockIdx.x * ROW_UNROLL;
    const bool full_strip = (row0 + ROW_UNROLL <= nrows);

    // ---- issue the block's strip loads FIRST (independent of the mask) ----
    // 8 front-batched LDG.128 per thread; softmax latency hides under them.
    float4 v[ROW_UNROLL];
    if (full_strip) {
        #pragma unroll
        for (int r = 0; r < ROW_UNROLL; r++)
            v[r] = __ldcs(&x4[base + (size_t)r * rowq]);
    }

    // ---- softmax computed while the loads are in flight ----
    float4 p = mask_param4[t];

    float m = fmaxf(fmaxf(p.x, p.y), fmaxf(p.z, p.w));
    #pragma unroll
    for (int o = 16; o; o >>= 1) m = fmaxf(m, __shfl_xor_sync(0xFFFFFFFFu, m, o));
    if ((t & 31) == 0) red[t >> 5] = m;
    __syncthreads();
    float maxv = red[0];
    #pragma unroll
    for (int i = 1; i < 8; i++) maxv = fmaxf(maxv, red[i]);
    __syncthreads();

    float e0 = __expf(p.x - maxv);
    float e1 = __expf(p.y - maxv);
    float e2 = __expf(p.z - maxv);
    float e3 = __expf(p.w - maxv);

    float s = e0 + e1 + e2 + e3;
    #pragma unroll
    for (int o = 16; o; o >>= 1) s += __shfl_xor_sync(0xFFFFFFFFu, s, o);
    if ((t & 31) == 0) red[t >> 5] = s;
    __syncthreads();
    float sum = 0.f;
    #pragma unroll
    for (int i = 0; i < 8; i++) sum += red[i];

    float4 mv = mvec4[t];
    float inv = (float)DIM / sum;   // PRUNE_RATE = 1.0
    float4 mk;
    mk.x = e0 * inv * mv.x;
    mk.y = e1 * inv * mv.y;
    mk.z = e2 * inv * mv.z;
    mk.w = e3 * inv * mv.w;

    // mask tail: out[n .. n+1023], written once by block 0
    if (blockIdx.x == 0)
        out4[(size_t)nrows * rowq + t] = mk;

    // ---- multiply + store the strip ----
    if (full_strip) {
        #pragma unroll
        for (int r = 0; r < ROW_UNROLL; r++) {
            v[r].x *= mk.x; v[r].y *= mk.y; v[r].z *= mk.z; v[r].w *= mk.w;
        }
        #pragma unroll
        for (int r = 0; r < ROW_UNROLL; r++)
            __stcs(&out4[base + (size_t)r * rowq], v[r]);
    } else {
        // partial strip at the end (bench shape divides evenly; safety path)
        for (int row = row0; row < nrows; row++, base += rowq) {
            float4 w = __ldcs(&x4[base]);
            w.x *= mk.x; w.y *= mk.y; w.z *= mk.z; w.w *= mk.w;
            __stcs(&out4[base], w);
        }
    }
}

extern "C" void kernel_launch(void* const* d_in, const int* in_sizes, int n_in,
                              void* d_out, int out_size) {
    const float* x          = (const float*)d_in[0];  // [8,4096,1024] fp32
    const float* mask_param = (const float*)d_in[1];  // [1024]
    const float* mvec       = (const float*)d_in[2];  // [1024]

    int n = in_sizes[0];
    int nrows = n / DIM;
    int blocks = (nrows + ROW_UNROLL - 1) / ROW_UNROLL;  // 4096 for bench shape

    fused_mask_mul_kernel<<<blocks, TPB>>>(
        (const float4*)x, (const float4*)mask_param, (const float4*)mvec,
        (float4*)d_out, nrows);
}

// round 12
// speedup vs baseline: 1.0383x; 1.0088x over previous
#include <cuda_runtime.h>

#define DIM 1024
#define TPB 256          // thread t owns float4 column t of each 1024-float row
#define ROW_UNROLL 8     // 4096 blocks * 8 rows = 32768 rows, exact

__global__ __launch_bounds__(TPB) void fused_mask_mul_kernel(
    const float4* __restrict__ x4,
    const float4* __restrict__ mask_param4,
    const float4* __restrict__ mvec4,
    float4* __restrict__ out4,
    int nrows)                      // nrows = n / 1024
{
    const int t = threadIdx.x;
    __shared__ float red[8];        // 8 warps per block

    const size_t rowq = DIM / 4;
    size_t base = (size_t)blockIdx.x * ROW_UNROLL * rowq + t;
    const int row0 = blockIdx.x * ROW_UNROLL;
    const bool full_strip = (row0 + ROW_UNROLL <= nrows);

    // ---- issue the block's strip loads FIRST (independent of the mask) ----
    // 8 front-batched LDG.128 per thread; softmax latency hides under them.
    float4 v[ROW_UNROLL];
    if (full_strip) {
        #pragma unroll
        for (int r = 0; r < ROW_UNROLL; r++)
            v[r] = __ldcs(&x4[base + (size_t)r * rowq]);
    }

    // ---- softmax computed while the loads are in flight ----
    float4 p = mask_param4[t];

    float m = fmaxf(fmaxf(p.x, p.y), fmaxf(p.z, p.w));
    #pragma unroll
    for (int o = 16; o; o >>= 1) m = fmaxf(m, __shfl_xor_sync(0xFFFFFFFFu, m, o));
    if ((t & 31) == 0) red[t >> 5] = m;
    __syncthreads();
    float maxv = red[0];
    #pragma unroll
    for (int i = 1; i < 8; i++) maxv = fmaxf(maxv, red[i]);
    __syncthreads();

    float e0 = __expf(p.x - maxv);
    float e1 = __expf(p.y - maxv);
    float e2 = __expf(p.z - maxv);
    float e3 = __expf(p.w - maxv);

    float s = e0 + e1 + e2 + e3;
    #pragma unroll
    for (int o = 16; o; o >>= 1) s += __shfl_xor_sync(0xFFFFFFFFu, s, o);
    if ((t & 31) == 0) red[t >> 5] = s;
    __syncthreads();
    float sum = 0.f;
    #pragma unroll
    for (int i = 0; i < 8; i++) sum += red[i];

    float4 mv = mvec4[t];
    float inv = (float)DIM / sum;   // PRUNE_RATE = 1.0
    float4 mk;
    mk.x = e0 * inv * mv.x;
    mk.y = e1 * inv * mv.y;
    mk.z = e2 * inv * mv.z;
    mk.w = e3 * inv * mv.w;

    // mask tail: out[n .. n+1023], written once by block 0
    if (blockIdx.x == 0)
        out4[(size_t)nrows * rowq + t] = mk;

    // ---- multiply + store fused per row: first stores issue as soon as
    //      the first loads land, overlapping STG issue with load latency ----
    if (full_strip) {
        #pragma unroll
        for (int r = 0; r < ROW_UNROLL; r++) {
            v[r].x *= mk.x; v[r].y *= mk.y; v[r].z *= mk.z; v[r].w *= mk.w;
            __stcs(&out4[base + (size_t)r * rowq], v[r]);
        }
    } else {
        // partial strip at the end (bench shape divides evenly; safety path)
        for (int row = row0; row < nrows; row++, base += rowq) {
            float4 w = __ldcs(&x4[base]);
            w.x *= mk.x; w.y *= mk.y; w.z *= mk.z; w.w *= mk.w;
            __stcs(&out4[base], w);
        }
    }
}

extern "C" void kernel_launch(void* const* d_in, const int* in_sizes, int n_in,
                              void* d_out, int out_size) {
    const float* x          = (const float*)d_in[0];  // [8,4096,1024] fp32
    const float* mask_param = (const float*)d_in[1];  // [1024]
    const float* mvec       = (const float*)d_in[2];  // [1024]

    int n = in_sizes[0];
    int nrows = n / DIM;
    int blocks = (nrows + ROW_UNROLL - 1) / ROW_UNROLL;  // 4096 for bench shape

    fused_mask_mul_kernel<<<blocks, TPB>>>(
        (const float4*)x, (const float4*)mask_param, (const float4*)mvec,
        (float4*)d_out, nrows);
}